// round 15
// baseline (speedup 1.0000x reference)
#include <cuda_runtime.h>

#define HW   4096
#define C    128
#define CR   32
#define G    8
#define CG   16
#define KK   49
#define KKG  392
#define NPX  16384   // B * H * W

typedef unsigned long long u64;

// ---- packed f32x2 helpers (sm_103a) ---------------------------------------
__device__ __forceinline__ u64 pack2(float x, float y) {
    u64 r; asm("mov.b64 %0, {%1, %2};" : "=l"(r) : "f"(x), "f"(y)); return r;
}
__device__ __forceinline__ void unpack2(u64 v, float& x, float& y) {
    asm("mov.b64 {%0, %1}, %2;" : "=f"(x), "=f"(y) : "l"(v));
}
__device__ __forceinline__ void ffma2(u64& d, u64 a, u64 b) {
    asm("fma.rn.f32x2 %0, %1, %2, %0;" : "+l"(d) : "l"(a), "l"(b));
}

// Scratch (16B-aligned)
__device__ __align__(16) float g_red[CR * NPX];        // [k][px]  k-major
__device__ __align__(16) float g_ker[4 * KKG * HW];    // [b][392][hw]

// ---------------------------------------------------------------------------
// Kernel 1: red[k][px] (R11-proven). Block 256, tile 64 px, grid 256.
// ---------------------------------------------------------------------------
__global__ __launch_bounds__(256) void k_reduce(const float* __restrict__ x,
                                                const float* __restrict__ wr,
                                                const float* __restrict__ br) {
    __shared__ u64 xsd[C * 32];        // [c][p2], 32 KB
    __shared__ u64 wsd[C * 33];        // [c][o] duplicated (w,w), stride 33
    const int tid  = threadIdx.x;
    const int lane = tid & 31;
    const int warp = tid >> 5;
    const int px0  = blockIdx.x * 64;
    const int b    = px0 >> 12;
    const int hw0  = px0 & 4095;
    const float* xb = x + (size_t)b * C * HW + hw0;

#pragma unroll
    for (int l = 0; l < 16; l++) {
        int idx = tid + l * 256;
        int c = idx >> 5, p2 = idx & 31;
        float2 v = *(const float2*)&xb[(size_t)c * HW + 2 * p2];
        xsd[c * 32 + p2] = pack2(v.x, v.y);
    }
#pragma unroll
    for (int l = 0; l < 16; l++) {
        int idx = tid + l * 256;
        int c = idx & 127, o = idx >> 7;
        float v = wr[o * C + c];
        wsd[c * 33 + o] = pack2(v, v);
    }
    __syncthreads();

    const int wo = warp * 4;
    u64 acc[4];
#pragma unroll
    for (int j = 0; j < 4; j++) {
        float bj = br[wo + j];
        acc[j] = pack2(bj, bj);
    }
#pragma unroll 8
    for (int k = 0; k < C; k++) {
        const u64 a = xsd[k * 32 + lane];
#pragma unroll
        for (int j = 0; j < 4; j++)
            ffma2(acc[j], a, wsd[k * 33 + wo + j]);
    }
#pragma unroll
    for (int j = 0; j < 4; j++) {
        float f0, f1; unpack2(acc[j], f0, f1);
        *(float2*)&g_red[(size_t)(wo + j) * NPX + px0 + 2 * lane] = make_float2(f0, f1);
    }
}

// ---------------------------------------------------------------------------
// Kernel 2: span (R11-proven shape): 256 px x 56 outs, grid (64,7).
// ---------------------------------------------------------------------------
__global__ __launch_bounds__(256) void k_span(const float* __restrict__ wsp,
                                              const float* __restrict__ bs) {
    __shared__ float rs[CR][258];
    __shared__ float ws[56 * 32];
    const int tid  = threadIdx.x;
    const int lane = tid & 31;
    const int warp = tid >> 5;
    const int px0  = blockIdx.x * 256;
    const int o0   = blockIdx.y * 56;
    const int b    = px0 >> 12;
    const int hw0  = px0 & 4095;

#pragma unroll
    for (int l = 0; l < 32; l++) {
        int idx = tid + l * 256;
        int k = idx >> 8, px = idx & 255;
        rs[k][px] = g_red[(size_t)k * NPX + px0 + px];
    }
#pragma unroll
    for (int l = 0; l < 7; l++) {
        int idx = tid + l * 256;
        ws[idx] = wsp[o0 * 32 + idx];
    }
    __syncthreads();

    u64 acc[4][7] = {};
#pragma unroll
    for (int k = 0; k < 32; k++) {
        u64 a[4];
#pragma unroll
        for (int v = 0; v < 4; v++)
            a[v] = *(const u64*)&rs[k][2 * lane + 64 * v];
#pragma unroll
        for (int j = 0; j < 7; j++) {
            const float bv = ws[(warp * 7 + j) * 32 + k];
            const u64 b2 = pack2(bv, bv);
#pragma unroll
            for (int v = 0; v < 4; v++) ffma2(acc[v][j], a[v], b2);
        }
    }
#pragma unroll
    for (int j = 0; j < 7; j++) {
        const int o = o0 + warp * 7 + j;
        const float bias = bs[o];
        float* kp = g_ker + ((size_t)b * KKG + o) * HW + hw0;
#pragma unroll
        for (int v = 0; v < 4; v++) {
            float f0, f1; unpack2(acc[v][j], f0, f1);
            *(float2*)&kp[2 * lane + 64 * v] = make_float2(f0 + bias, f1 + bias);
        }
    }
}

// ---------------------------------------------------------------------------
// Kernel 3: involution, 4 px/thread. Block 256 (16x16) covers 64x16 px
// (full image width). Grid (1,4,32) = 128 CTAs -> 1 CTA/SM, single wave,
// register budget effectively unlimited (<=255).
// Per (channel, tap-row): 4 LDS.128 load the 16-float row segment; its even
// u64 register pairs are the 8 tap operands -> 14 FFMA2 per 4 accesses.
// kv (2 u64 per tap, per-pixel kernel) prefetched one row ahead (L2 hides).
// 8 channels staged per round (71.7KB dynamic smem), 2 rounds.
// ---------------------------------------------------------------------------
#define SMEM_INV (8 * 28 * 80 * 4)   // 71680 B

__global__ __launch_bounds__(256) void k_inv(const float* __restrict__ x,
                                             float* __restrict__ out) {
    extern __shared__ float xs[];      // [8 ch][28 r][80 c]
    const int tx = threadIdx.x, ty = threadIdx.y;   // (16,16)
    const int tid = ty * 16 + tx;
    const int ty0 = blockIdx.y * 16;
    const int bg  = blockIdx.z;
    const int b = bg >> 3, g = bg & 7;
    const int pix = (ty0 + ty) * 64 + 4 * tx;       // 16B-aligned px base

    const float* kb = g_ker + ((size_t)b * KKG + g * KK) * HW + pix;
    const float* xb = x + ((size_t)b * C + g * CG) * HW;
    float* ob = out + ((size_t)b * C + g * CG) * HW + pix;

    for (int c0 = 0; c0 < CG; c0 += 8) {
        __syncthreads();
        // stage 8 channels: 28 rows x 76 cols each (global cols -6..69)
#pragma unroll
        for (int ch = 0; ch < 8; ch++) {
            const float* xc = xb + (size_t)(c0 + ch) * HW;
#pragma unroll
            for (int l = 0; l < 9; l++) {
                int idx = tid + l * 256;
                if (idx < 28 * 76) {
                    int r   = idx / 76;
                    int col = idx - r * 76;
                    int gy = ty0 - 6 + r, gx = col - 6;
                    float v = 0.f;
                    if (gy >= 0 && gy < 64 && gx >= 0 && gx < 64)
                        v = xc[gy * 64 + gx];
                    xs[(ch * 28 + r) * 80 + col] = v;
                }
            }
        }
        __syncthreads();

        u64 acc[8][2] = {};

        // prefetch kv for tap-row 0
        u64 kva[7], kvb[7];
#pragma unroll
        for (int j = 0; j < 7; j++) {
            kva[j] = *(const u64*)&kb[(size_t)j * HW];
            kvb[j] = *(const u64*)&kb[(size_t)j * HW + 2];
        }

#pragma unroll
        for (int i = 0; i < 7; i++) {
            u64 na[7], nb2[7];
            if (i < 6) {
#pragma unroll
                for (int j = 0; j < 7; j++) {
                    na[j]  = *(const u64*)&kb[(size_t)((i + 1) * 7 + j) * HW];
                    nb2[j] = *(const u64*)&kb[(size_t)((i + 1) * 7 + j) * HW + 2];
                }
            }

            const int row = ty + 2 * i;
#pragma unroll
            for (int ch = 0; ch < 8; ch++) {
                const float* bp = &xs[(ch * 28 + row) * 80 + 4 * tx];
                const float4 s0 = *(const float4*)(bp);
                const float4 s1 = *(const float4*)(bp + 4);
                const float4 s2 = *(const float4*)(bp + 8);
                const float4 s3 = *(const float4*)(bp + 12);
                u64 u[8];
                u[0] = pack2(s0.x, s0.y); u[1] = pack2(s0.z, s0.w);
                u[2] = pack2(s1.x, s1.y); u[3] = pack2(s1.z, s1.w);
                u[4] = pack2(s2.x, s2.y); u[5] = pack2(s2.z, s2.w);
                u[6] = pack2(s3.x, s3.y); u[7] = pack2(s3.z, s3.w);
#pragma unroll
                for (int j = 0; j < 7; j++) {
                    ffma2(acc[ch][0], u[j],     kva[j]);
                    ffma2(acc[ch][1], u[j + 1], kvb[j]);
                }
            }

            if (i < 6) {
#pragma unroll
                for (int j = 0; j < 7; j++) { kva[j] = na[j]; kvb[j] = nb2[j]; }
            }
        }

#pragma unroll
        for (int ch = 0; ch < 8; ch++) {
            float a0, a1, b0, b1;
            unpack2(acc[ch][0], a0, a1);
            unpack2(acc[ch][1], b0, b1);
            *(float4*)&ob[(size_t)(c0 + ch) * HW] = make_float4(a0, a1, b0, b1);
        }
    }
}

// ---------------------------------------------------------------------------
extern "C" void kernel_launch(void* const* d_in, const int* in_sizes, int n_in,
                              void* d_out, int out_size) {
    const float* x   = (const float*)d_in[0];   // [4,128,64,64]
    const float* wr  = (const float*)d_in[1];   // [32,128]
    const float* br  = (const float*)d_in[2];   // [32]
    const float* wsp = (const float*)d_in[3];   // [392,32]
    const float* bsp = (const float*)d_in[4];   // [392]
    float* out = (float*)d_out;

    cudaFuncSetAttribute(k_inv, cudaFuncAttributeMaxDynamicSharedMemorySize,
                         SMEM_INV);

    k_reduce<<<256, 256>>>(x, wr, br);
    k_span<<<dim3(64, 7), 256>>>(wsp, bsp);
    k_inv<<<dim3(1, 4, 32), dim3(16, 16), SMEM_INV>>>(x, out);
}

// round 16
// speedup vs baseline: 1.2829x; 1.2829x over previous
#include <cuda_runtime.h>

#define HW   4096
#define C    128
#define CR   32
#define G    8
#define CG   16
#define KK   49
#define KKG  392
#define NPX  16384   // B * H * W

typedef unsigned long long u64;

// ---- packed f32x2 helpers (sm_103a) ---------------------------------------
__device__ __forceinline__ u64 pack2(float x, float y) {
    u64 r; asm("mov.b64 %0, {%1, %2};" : "=l"(r) : "f"(x), "f"(y)); return r;
}
__device__ __forceinline__ void unpack2(u64 v, float& x, float& y) {
    asm("mov.b64 {%0, %1}, %2;" : "=f"(x), "=f"(y) : "l"(v));
}
__device__ __forceinline__ void ffma2(u64& d, u64 a, u64 b) {
    asm("fma.rn.f32x2 %0, %1, %2, %0;" : "+l"(d) : "l"(a), "l"(b));
}

// Scratch (16B-aligned)
__device__ __align__(16) float g_red[CR * NPX];        // [k][px]  k-major
__device__ __align__(16) float g_ker[4 * KKG * HW];    // [b][392][hw]

// ---------------------------------------------------------------------------
// Kernel 1: red[k][px] (R11-proven). Block 256, tile 64 px, grid 256.
// ---------------------------------------------------------------------------
__global__ __launch_bounds__(256) void k_reduce(const float* __restrict__ x,
                                                const float* __restrict__ wr,
                                                const float* __restrict__ br) {
    __shared__ u64 xsd[C * 32];        // [c][p2], 32 KB
    __shared__ u64 wsd[C * 33];        // [c][o] duplicated (w,w), stride 33
    const int tid  = threadIdx.x;
    const int lane = tid & 31;
    const int warp = tid >> 5;
    const int px0  = blockIdx.x * 64;
    const int b    = px0 >> 12;
    const int hw0  = px0 & 4095;
    const float* xb = x + (size_t)b * C * HW + hw0;

#pragma unroll
    for (int l = 0; l < 16; l++) {
        int idx = tid + l * 256;
        int c = idx >> 5, p2 = idx & 31;
        float2 v = *(const float2*)&xb[(size_t)c * HW + 2 * p2];
        xsd[c * 32 + p2] = pack2(v.x, v.y);
    }
#pragma unroll
    for (int l = 0; l < 16; l++) {
        int idx = tid + l * 256;
        int c = idx & 127, o = idx >> 7;
        float v = wr[o * C + c];
        wsd[c * 33 + o] = pack2(v, v);
    }
    __syncthreads();

    const int wo = warp * 4;
    u64 acc[4];
#pragma unroll
    for (int j = 0; j < 4; j++) {
        float bj = br[wo + j];
        acc[j] = pack2(bj, bj);
    }
#pragma unroll 8
    for (int k = 0; k < C; k++) {
        const u64 a = xsd[k * 32 + lane];
#pragma unroll
        for (int j = 0; j < 4; j++)
            ffma2(acc[j], a, wsd[k * 33 + wo + j]);
    }
#pragma unroll
    for (int j = 0; j < 4; j++) {
        float f0, f1; unpack2(acc[j], f0, f1);
        *(float2*)&g_red[(size_t)(wo + j) * NPX + px0 + 2 * lane] = make_float2(f0, f1);
    }
}

// ---------------------------------------------------------------------------
// Kernel 2: span (R11-proven shape): 256 px x 56 outs, grid (64,7).
// ---------------------------------------------------------------------------
__global__ __launch_bounds__(256) void k_span(const float* __restrict__ wsp,
                                              const float* __restrict__ bs) {
    __shared__ float rs[CR][258];
    __shared__ float ws[56 * 32];
    const int tid  = threadIdx.x;
    const int lane = tid & 31;
    const int warp = tid >> 5;
    const int px0  = blockIdx.x * 256;
    const int o0   = blockIdx.y * 56;
    const int b    = px0 >> 12;
    const int hw0  = px0 & 4095;

#pragma unroll
    for (int l = 0; l < 32; l++) {
        int idx = tid + l * 256;
        int k = idx >> 8, px = idx & 255;
        rs[k][px] = g_red[(size_t)k * NPX + px0 + px];
    }
#pragma unroll
    for (int l = 0; l < 7; l++) {
        int idx = tid + l * 256;
        ws[idx] = wsp[o0 * 32 + idx];
    }
    __syncthreads();

    u64 acc[4][7] = {};
#pragma unroll
    for (int k = 0; k < 32; k++) {
        u64 a[4];
#pragma unroll
        for (int v = 0; v < 4; v++)
            a[v] = *(const u64*)&rs[k][2 * lane + 64 * v];
#pragma unroll
        for (int j = 0; j < 7; j++) {
            const float bv = ws[(warp * 7 + j) * 32 + k];
            const u64 b2 = pack2(bv, bv);
#pragma unroll
            for (int v = 0; v < 4; v++) ffma2(acc[v][j], a[v], b2);
        }
    }
#pragma unroll
    for (int j = 0; j < 7; j++) {
        const int o = o0 + warp * 7 + j;
        const float bias = bs[o];
        float* kp = g_ker + ((size_t)b * KKG + o) * HW + hw0;
#pragma unroll
        for (int v = 0; v < 4; v++) {
            float f0, f1; unpack2(acc[v][j], f0, f1);
            *(float2*)&kp[2 * lane + 64 * v] = make_float2(f0 + bias, f1 + bias);
        }
    }
}

// ---------------------------------------------------------------------------
// Kernel 3: involution — R11 winner, ONE change: __launch_bounds__(256, 2)
// to force regs<=128 -> 2 CTAs/SM -> all 256 CTAs co-resident, 16 warps/SM.
// ---------------------------------------------------------------------------
__global__ __launch_bounds__(256, 2) void k_inv(const float* __restrict__ x,
                                                float* __restrict__ out) {
    __shared__ float xs[2][2][28][48];   // [buf][ch][row][col]
    const int tx = threadIdx.x, ty = threadIdx.y;   // (16,16)
    const int tid = ty * 16 + tx;
    const int tx0 = blockIdx.x * 32, ty0 = blockIdx.y * 16;
    const int bg = blockIdx.z;
    const int b = bg >> 3, g = bg & 7;
    const int pix = (ty0 + ty) * 64 + tx0 + 2 * tx;

    const float* kb = g_ker + ((size_t)b * KKG + g * KK) * HW + pix;
    u64 kreg[49];
#pragma unroll
    for (int kk = 0; kk < 49; kk++) kreg[kk] = *(const u64*)&kb[(size_t)kk * HW];

    const float* xb = x + ((size_t)b * C + g * CG) * HW;
    float* ob = out + ((size_t)b * C + g * CG) * HW + pix;

#pragma unroll
    for (int cc = 0; cc < 2; cc++) {
        const float* xc = xb + (size_t)cc * HW;
#pragma unroll
        for (int l = 0; l < 5; l++) {
            int idx = tid + l * 256;
            if (idx < 28 * 44) {
                int r    = idx / 44;
                int ccol = idx - r * 44;
                int gy = ty0 - 6 + r, gx = tx0 - 6 + ccol;
                float v = 0.f;
                if (gy >= 0 && gy < 64 && gx >= 0 && gx < 64)
                    v = xc[gy * 64 + gx];
                xs[0][cc][r][ccol] = v;
            }
        }
    }
    __syncthreads();

    for (int rnd = 0; rnd < 8; rnd++) {
        const int cur = rnd & 1;
        const int c0  = rnd * 2;

        float pf[10];
        if (rnd < 7) {
#pragma unroll
            for (int cc = 0; cc < 2; cc++) {
                const float* xc = xb + (size_t)(c0 + 2 + cc) * HW;
#pragma unroll
                for (int l = 0; l < 5; l++) {
                    int idx = tid + l * 256;
                    float v = 0.f;
                    if (idx < 28 * 44) {
                        int r    = idx / 44;
                        int ccol = idx - r * 44;
                        int gy = ty0 - 6 + r, gx = tx0 - 6 + ccol;
                        if (gy >= 0 && gy < 64 && gx >= 0 && gx < 64)
                            v = xc[gy * 64 + gx];
                    }
                    pf[cc * 5 + l] = v;
                }
            }
        }

#pragma unroll
        for (int cc = 0; cc < 2; cc++) {
            u64 a0 = 0, a1 = 0;
#pragma unroll
            for (int i = 0; i < 7; i++)
#pragma unroll
                for (int j = 0; j < 7; j++) {
                    const int t = i * 7 + j;
                    const u64 v = *(const u64*)&xs[cur][cc][ty + 2 * i][2 * tx + 2 * j];
                    if (t & 1) ffma2(a1, v, kreg[t]);
                    else       ffma2(a0, v, kreg[t]);
                }
            float e0, e1, o0v, o1v;
            unpack2(a0, e0, e1); unpack2(a1, o0v, o1v);
            *(float2*)&ob[(size_t)(c0 + cc) * HW] = make_float2(e0 + o0v, e1 + o1v);
        }

        if (rnd < 7) {
#pragma unroll
            for (int cc = 0; cc < 2; cc++)
#pragma unroll
                for (int l = 0; l < 5; l++) {
                    int idx = tid + l * 256;
                    if (idx < 28 * 44) {
                        int r    = idx / 44;
                        int ccol = idx - r * 44;
                        xs[1 - cur][cc][r][ccol] = pf[cc * 5 + l];
                    }
                }
            __syncthreads();
        }
    }
}

// ---------------------------------------------------------------------------
extern "C" void kernel_launch(void* const* d_in, const int* in_sizes, int n_in,
                              void* d_out, int out_size) {
    const float* x   = (const float*)d_in[0];   // [4,128,64,64]
    const float* wr  = (const float*)d_in[1];   // [32,128]
    const float* br  = (const float*)d_in[2];   // [32]
    const float* wsp = (const float*)d_in[3];   // [392,32]
    const float* bsp = (const float*)d_in[4];   // [392]
    float* out = (float*)d_out;

    k_reduce<<<256, 256>>>(x, wr, br);
    k_span<<<dim3(64, 7), 256>>>(wsp, bsp);
    k_inv<<<dim3(2, 4, 32), dim3(16, 16)>>>(x, out);
}

// round 17
// speedup vs baseline: 1.3831x; 1.0781x over previous
#include <cuda_runtime.h>

#define HW   4096
#define C    128
#define CR   32
#define G    8
#define CG   16
#define KK   49
#define KKG  392
#define NPX  16384   // B * H * W

typedef unsigned long long u64;

// ---- packed f32x2 helpers (sm_103a) ---------------------------------------
__device__ __forceinline__ u64 pack2(float x, float y) {
    u64 r; asm("mov.b64 %0, {%1, %2};" : "=l"(r) : "f"(x), "f"(y)); return r;
}
__device__ __forceinline__ void unpack2(u64 v, float& x, float& y) {
    asm("mov.b64 {%0, %1}, %2;" : "=f"(x), "=f"(y) : "l"(v));
}
__device__ __forceinline__ void ffma2(u64& d, u64 a, u64 b) {
    asm("fma.rn.f32x2 %0, %1, %2, %0;" : "+l"(d) : "l"(a), "l"(b));
}

// Scratch (16B-aligned)
__device__ __align__(16) float g_red[CR * NPX];        // [k][px]  k-major
__device__ __align__(16) float g_ker[4 * KKG * HW];    // [b][392][hw]

// ---------------------------------------------------------------------------
// Kernel 1: red[k][px] (R11-proven). Block 256, tile 64 px, grid 256.
// ---------------------------------------------------------------------------
__global__ __launch_bounds__(256) void k_reduce(const float* __restrict__ x,
                                                const float* __restrict__ wr,
                                                const float* __restrict__ br) {
    __shared__ u64 xsd[C * 32];        // [c][p2], 32 KB
    __shared__ u64 wsd[C * 33];        // [c][o] duplicated (w,w), stride 33
    const int tid  = threadIdx.x;
    const int lane = tid & 31;
    const int warp = tid >> 5;
    const int px0  = blockIdx.x * 64;
    const int b    = px0 >> 12;
    const int hw0  = px0 & 4095;
    const float* xb = x + (size_t)b * C * HW + hw0;

#pragma unroll
    for (int l = 0; l < 16; l++) {
        int idx = tid + l * 256;
        int c = idx >> 5, p2 = idx & 31;
        float2 v = *(const float2*)&xb[(size_t)c * HW + 2 * p2];
        xsd[c * 32 + p2] = pack2(v.x, v.y);
    }
#pragma unroll
    for (int l = 0; l < 16; l++) {
        int idx = tid + l * 256;
        int c = idx & 127, o = idx >> 7;
        float v = wr[o * C + c];
        wsd[c * 33 + o] = pack2(v, v);
    }
    __syncthreads();

    const int wo = warp * 4;
    u64 acc[4];
#pragma unroll
    for (int j = 0; j < 4; j++) {
        float bj = br[wo + j];
        acc[j] = pack2(bj, bj);
    }
#pragma unroll 8
    for (int k = 0; k < C; k++) {
        const u64 a = xsd[k * 32 + lane];
#pragma unroll
        for (int j = 0; j < 4; j++)
            ffma2(acc[j], a, wsd[k * 33 + wo + j]);
    }
#pragma unroll
    for (int j = 0; j < 4; j++) {
        float f0, f1; unpack2(acc[j], f0, f1);
        *(float2*)&g_red[(size_t)(wo + j) * NPX + px0 + 2 * lane] = make_float2(f0, f1);
    }
}

// ---------------------------------------------------------------------------
// Kernel 2: span (R11 shape) + __launch_bounds__(256,2) occupancy cap.
// 256 px x 56 outs, grid (64,7) = 448 CTAs; 2 CTAs/SM -> 1.5 waves.
// ---------------------------------------------------------------------------
__global__ __launch_bounds__(256, 2) void k_span(const float* __restrict__ wsp,
                                                 const float* __restrict__ bs) {
    __shared__ float rs[CR][258];
    __shared__ float ws[56 * 32];
    const int tid  = threadIdx.x;
    const int lane = tid & 31;
    const int warp = tid >> 5;
    const int px0  = blockIdx.x * 256;
    const int o0   = blockIdx.y * 56;
    const int b    = px0 >> 12;
    const int hw0  = px0 & 4095;

#pragma unroll
    for (int l = 0; l < 32; l++) {
        int idx = tid + l * 256;
        int k = idx >> 8, px = idx & 255;
        rs[k][px] = g_red[(size_t)k * NPX + px0 + px];
    }
#pragma unroll
    for (int l = 0; l < 7; l++) {
        int idx = tid + l * 256;
        ws[idx] = wsp[o0 * 32 + idx];
    }
    __syncthreads();

    u64 acc[4][7] = {};
#pragma unroll
    for (int k = 0; k < 32; k++) {
        u64 a[4];
#pragma unroll
        for (int v = 0; v < 4; v++)
            a[v] = *(const u64*)&rs[k][2 * lane + 64 * v];
#pragma unroll
        for (int j = 0; j < 7; j++) {
            const float bv = ws[(warp * 7 + j) * 32 + k];
            const u64 b2 = pack2(bv, bv);
#pragma unroll
            for (int v = 0; v < 4; v++) ffma2(acc[v][j], a[v], b2);
        }
    }
#pragma unroll
    for (int j = 0; j < 7; j++) {
        const int o = o0 + warp * 7 + j;
        const float bias = bs[o];
        float* kp = g_ker + ((size_t)b * KKG + o) * HW + hw0;
#pragma unroll
        for (int v = 0; v < 4; v++) {
            float f0, f1; unpack2(acc[v][j], f0, f1);
            *(float2*)&kp[2 * lane + 64 * v] = make_float2(f0 + bias, f1 + bias);
        }
    }
}

// ---------------------------------------------------------------------------
// Kernel 3: involution — R16 champion (launch_bounds(256,2)) with staging
// index math hoisted: soff/goff/ok depend only on l, computed once.
// ---------------------------------------------------------------------------
__global__ __launch_bounds__(256, 2) void k_inv(const float* __restrict__ x,
                                                float* __restrict__ out) {
    __shared__ float xs[2][2][28][48];   // [buf][ch][row][col]
    const int tx = threadIdx.x, ty = threadIdx.y;   // (16,16)
    const int tid = ty * 16 + tx;
    const int tx0 = blockIdx.x * 32, ty0 = blockIdx.y * 16;
    const int bg = blockIdx.z;
    const int b = bg >> 3, g = bg & 7;
    const int pix = (ty0 + ty) * 64 + tx0 + 2 * tx;

    // hoisted staging geometry (per-l, independent of round/channel)
    int  soff[5];   // smem offset r*48+ccol
    int  goff[5];   // gmem offset gy*64+gx (clamped)
    bool ok[5];     // in-bounds
#pragma unroll
    for (int l = 0; l < 5; l++) {
        int idx = tid + l * 256;
        if (idx < 28 * 44) {
            int r    = idx / 44;
            int ccol = idx - r * 44;
            int gy = ty0 - 6 + r, gx = tx0 - 6 + ccol;
            soff[l] = r * 48 + ccol;
            ok[l]   = (gy >= 0 && gy < 64 && gx >= 0 && gx < 64);
            goff[l] = ok[l] ? gy * 64 + gx : 0;
        } else {
            soff[l] = -1; ok[l] = false; goff[l] = 0;
        }
    }

    const float* kb = g_ker + ((size_t)b * KKG + g * KK) * HW + pix;
    u64 kreg[49];
#pragma unroll
    for (int kk = 0; kk < 49; kk++) kreg[kk] = *(const u64*)&kb[(size_t)kk * HW];

    const float* xb = x + ((size_t)b * C + g * CG) * HW;
    float* ob = out + ((size_t)b * C + g * CG) * HW + pix;

#pragma unroll
    for (int cc = 0; cc < 2; cc++) {
        const float* xc = xb + (size_t)cc * HW;
#pragma unroll
        for (int l = 0; l < 5; l++) {
            if (soff[l] >= 0)
                (&xs[0][cc][0][0])[soff[l]] = ok[l] ? xc[goff[l]] : 0.f;
        }
    }
    __syncthreads();

    for (int rnd = 0; rnd < 8; rnd++) {
        const int cur = rnd & 1;
        const int c0  = rnd * 2;

        float pf[10];
        if (rnd < 7) {
#pragma unroll
            for (int cc = 0; cc < 2; cc++) {
                const float* xc = xb + (size_t)(c0 + 2 + cc) * HW;
#pragma unroll
                for (int l = 0; l < 5; l++)
                    pf[cc * 5 + l] = ok[l] ? xc[goff[l]] : 0.f;
            }
        }

#pragma unroll
        for (int cc = 0; cc < 2; cc++) {
            u64 a0 = 0, a1 = 0;
#pragma unroll
            for (int i = 0; i < 7; i++)
#pragma unroll
                for (int j = 0; j < 7; j++) {
                    const int t = i * 7 + j;
                    const u64 v = *(const u64*)&xs[cur][cc][ty + 2 * i][2 * tx + 2 * j];
                    if (t & 1) ffma2(a1, v, kreg[t]);
                    else       ffma2(a0, v, kreg[t]);
                }
            float e0, e1, o0v, o1v;
            unpack2(a0, e0, e1); unpack2(a1, o0v, o1v);
            *(float2*)&ob[(size_t)(c0 + cc) * HW] = make_float2(e0 + o0v, e1 + o1v);
        }

        if (rnd < 7) {
#pragma unroll
            for (int cc = 0; cc < 2; cc++)
#pragma unroll
                for (int l = 0; l < 5; l++) {
                    if (soff[l] >= 0)
                        (&xs[1 - cur][cc][0][0])[soff[l]] = pf[cc * 5 + l];
                }
            __syncthreads();
        }
    }
}

// ---------------------------------------------------------------------------
extern "C" void kernel_launch(void* const* d_in, const int* in_sizes, int n_in,
                              void* d_out, int out_size) {
    const float* x   = (const float*)d_in[0];   // [4,128,64,64]
    const float* wr  = (const float*)d_in[1];   // [32,128]
    const float* br  = (const float*)d_in[2];   // [32]
    const float* wsp = (const float*)d_in[3];   // [392,32]
    const float* bsp = (const float*)d_in[4];   // [392]
    float* out = (float*)d_out;

    k_reduce<<<256, 256>>>(x, wr, br);
    k_span<<<dim3(64, 7), 256>>>(wsp, bsp);
    k_inv<<<dim3(2, 4, 32), dim3(16, 16)>>>(x, out);
}